// round 12
// baseline (speedup 1.0000x reference)
#include <cuda_runtime.h>
#include <cuda_bf16.h>
#include <cstdint>
#include <math.h>

#define NDIM 8192
#define RANK 64
#define BM 128
#define BKC 64
#define KHALF (NDIM / 2)       // 4096
#define NCHH (KHALF / BKC)     // 64 chunks per CTA
#define QTHREADS 384           // 8 consumer warps + 4 producer warps
#define A_TILE (BM * 144)      // 18432
#define B_TILE (RANK * 144)    // 9216
#define STAGEB (A_TILE + B_TILE)
#define NSTG 3
#define QSMEM (NSTG * STAGEB + 1024)
#define NCTAS 256

// ---- device scratch (allocation-free rule) ----
__device__ double g_acc[3];                     // [0]=E1, [1]=quad_U, [2]=quad_V
__device__ unsigned int g_done;                 // CTA completion counter
__device__ float  g_Vt[NDIM * RANK];            // V^T fp32 [8192,64]
__device__ __nv_bfloat16 g_Bu[RANK * NDIM];     // U^T bf16 [64,8192] (MMA B)
__device__ __nv_bfloat16 g_Bv[RANK * NDIM];     // V   bf16 [64,8192] (MMA B)
__device__ __nv_bfloat16 g_Ub16[NDIM * RANK];   // U    bf16 [8192,64] (e1)
__device__ __nv_bfloat16 g_Vt16[NDIM * RANK];   // V^T  bf16 [8192,64] (e1)

__device__ __forceinline__ uint32_t smem_u32(const void* p) {
    uint32_t a;
    asm("{ .reg .u64 t; cvta.to.shared.u64 t, %1; cvt.u32.u64 %0, t; }"
        : "=r"(a) : "l"(p));
    return a;
}

#define BAR_SYNC(id)   asm volatile("bar.sync %0, 384;"   :: "r"(id) : "memory")
#define BAR_ARRIVE(id) asm volatile("bar.arrive %0, 384;" :: "r"(id) : "memory")

// ======================= prep (fused, grid.z selects) =======================
__global__ void prep_kernel(const float* __restrict__ V,
                            const float* __restrict__ U) {
    __shared__ float tile[32][33];
    if (blockIdx.z == 0) {
        int x = blockIdx.x * 32 + threadIdx.x;   // n
        int y = blockIdx.y * 32 + threadIdx.y;   // r
        float v = V[(size_t)y * NDIM + x];
        tile[threadIdx.y][threadIdx.x] = v;
        g_Bv[(size_t)y * NDIM + x] = __float2bfloat16(v);
        __syncthreads();
        int n = blockIdx.x * 32 + threadIdx.y;
        int r = blockIdx.y * 32 + threadIdx.x;
        float tv = tile[threadIdx.x][threadIdx.y];
        g_Vt[(size_t)n * RANK + r] = tv;
        g_Vt16[(size_t)n * RANK + r] = __float2bfloat16(tv);
        if (blockIdx.x == 0 && blockIdx.y == 0 && threadIdx.y == 0 &&
            threadIdx.x < 3)
            g_acc[threadIdx.x] = 0.0;
    } else {
        int i0 = blockIdx.x * 32, r0 = blockIdx.y * 32;
        float u = U[(size_t)(i0 + threadIdx.y) * RANK + r0 + threadIdx.x];
        tile[threadIdx.y][threadIdx.x] = u;
        g_Ub16[(size_t)(i0 + threadIdx.y) * RANK + r0 + threadIdx.x] =
            __float2bfloat16(u);
        __syncthreads();
        g_Bu[(size_t)(r0 + threadIdx.y) * NDIM + i0 + threadIdx.x] =
            __float2bfloat16(tile[threadIdx.x][threadIdx.y]);
    }
}

// ========== fused quad: warp-specialized producer/consumer + e1 ==========
// Warps 0..7: consumers (ldmatrix + HMMA only). Warps 8..11: producers
// (LDG fp32 -> cvt bf16 -> STS staging, plus ALL e1 gathers). 3-stage smem
// ring, named barriers full[s]=1+s / empty[s]=4+s (count 384). 2 CTAs/SM.
__global__ __launch_bounds__(QTHREADS, 2) void fused_kernel(
    const float* __restrict__ S_U, const float* __restrict__ U,
    const float* __restrict__ S_V, const float* __restrict__ vals,
    const int* __restrict__ rows, const int* __restrict__ cols,
    const float* __restrict__ sigma, float* __restrict__ out, int nobs) {
    extern __shared__ char dynsmem[];
    __shared__ float wsum[QTHREADS / 32];
    __shared__ float esum[QTHREADS / 32];

    const int t = threadIdx.x;
    const int wid = t >> 5, lane = t & 31;

    const float* S;
    const __nv_bfloat16* Bg;
    const float* Xf;
    int slot;
    if (blockIdx.z == 0) { S = S_U; Bg = g_Bu; Xf = U;    slot = 1; }
    else                 { S = S_V; Bg = g_Bv; Xf = g_Vt; slot = 2; }
    const int i0 = blockIdx.x * BM;
    const size_t kbase = (size_t)blockIdx.y * KHALF;
    const int ctaid = blockIdx.x + 64 * blockIdx.y + 128 * blockIdx.z; // 0..255

    const uint32_t base = (smem_u32(dynsmem) + 1023u) & ~1023u;

    if (wid < 8) {
        // ================= CONSUMERS =================
        const uint32_t a_lm = (uint32_t)(wid * 16 + (lane & 15)) * 144 +
                              (lane & 16);
        const uint32_t b_lm = (uint32_t)((lane & 7) + ((lane & 16) >> 1)) *
                                  144 + ((lane & 8) << 1);
        float acc[8][4];
        #pragma unroll
        for (int tn = 0; tn < 8; tn++)
            #pragma unroll
            for (int q = 0; q < 4; q++) acc[tn][q] = 0.f;

        for (int cc = 0; cc < NCHH; cc++) {
            int s = cc % NSTG;
            BAR_SYNC(1 + s);
            uint32_t ab = base + s * STAGEB, bb = ab + A_TILE;
            #pragma unroll
            for (int ss = 0; ss < 4; ss++) {
                uint32_t a[4];
                asm volatile("ldmatrix.sync.aligned.m8n8.x4.shared.b16 "
                             "{%0,%1,%2,%3}, [%4];"
                             : "=r"(a[0]), "=r"(a[1]), "=r"(a[2]), "=r"(a[3])
                             : "r"(ab + a_lm + ss * 32));
                uint32_t b[4][4];
                #pragma unroll
                for (int j = 0; j < 4; j++)
                    asm volatile("ldmatrix.sync.aligned.m8n8.x4.shared.b16 "
                                 "{%0,%1,%2,%3}, [%4];"
                                 : "=r"(b[j][0]), "=r"(b[j][1]),
                                   "=r"(b[j][2]), "=r"(b[j][3])
                                 : "r"(bb + b_lm + j * (16 * 144) + ss * 32));
                #pragma unroll
                for (int tn = 0; tn < 8; tn++)
                    asm volatile(
                        "mma.sync.aligned.m16n8k16.row.col.f32.bf16.bf16.f32 "
                        "{%0,%1,%2,%3}, {%4,%5,%6,%7}, {%8,%9}, "
                        "{%0,%1,%2,%3};"
                        : "+f"(acc[tn][0]), "+f"(acc[tn][1]),
                          "+f"(acc[tn][2]), "+f"(acc[tn][3])
                        : "r"(a[0]), "r"(a[1]), "r"(a[2]), "r"(a[3]),
                          "r"(b[tn >> 1][(tn & 1) * 2]),
                          "r"(b[tn >> 1][(tn & 1) * 2 + 1]));
            }
            BAR_ARRIVE(4 + s);
        }

        // quad epilogue: partial = sum of D[row][n] * X[row][n]
        const int g = lane >> 2, tg = lane & 3;
        const int r0 = i0 + wid * 16 + g;
        float partial = 0.f;
        #pragma unroll
        for (int tn = 0; tn < 8; tn++) {
            int n = tn * 8 + 2 * tg;
            float2 x0 = *(const float2*)(Xf + (size_t)r0 * RANK + n);
            float2 x1 = *(const float2*)(Xf + (size_t)(r0 + 8) * RANK + n);
            partial = fmaf(acc[tn][0], x0.x, partial);
            partial = fmaf(acc[tn][1], x0.y, partial);
            partial = fmaf(acc[tn][2], x1.x, partial);
            partial = fmaf(acc[tn][3], x1.y, partial);
        }
        #pragma unroll
        for (int o = 16; o; o >>= 1)
            partial += __shfl_xor_sync(0xffffffffu, partial, o);
        if (lane == 0) { wsum[wid] = partial; esum[wid] = 0.f; }
    } else {
        // ================= PRODUCERS =================
        const int pt = t - 256;                 // 0..127
        const int lg = lane >> 3, ls = lane & 7;
        const int e1base = ctaid * 4096 + (wid - 8) * 1024;
        // A: 16 granule-passes of 128 threads; closed-form bases
        const float* a_base = S + (size_t)(i0 + (pt >> 4)) * NDIM + kbase +
                              (pt & 15) * 4;
        const uint32_t a_st = (uint32_t)(pt >> 4) * 144 + (pt & 15) * 8;
        // B: 4 passes; 8 x 16B granules per 64-col bf16 row
        const __nv_bfloat16* b_base = Bg + (size_t)(pt >> 3) * NDIM + kbase +
                                      (pt & 7) * 8;
        const uint32_t b_st = (uint32_t)(pt >> 3) * 144 + (pt & 7) * 16;

        float e1sum = 0.f;
        float4 rA[8];
        uint4  rB[4];

#define E1_STEP4(j) do {                                                      \
    int o = e1base + (j) * 4 + lg;                                            \
    int oc = o < nobs ? o : nobs - 1;                                         \
    int r = rows[oc], c = cols[oc];                                           \
    uint4 ua = *(const uint4*)(g_Ub16 + (size_t)r * RANK + ls * 8);           \
    uint4 vb = *(const uint4*)(g_Vt16 + (size_t)c * RANK + ls * 8);           \
    float s2_ = 0.f;                                                          \
    {                                                                         \
        const uint32_t* up = &ua.x;                                           \
        const uint32_t* vp = &vb.x;                                           \
        _Pragma("unroll") for (int h = 0; h < 4; h++) {                       \
            float2 fu = __bfloat1622float2(*(const __nv_bfloat162*)&up[h]);   \
            float2 fv = __bfloat1622float2(*(const __nv_bfloat162*)&vp[h]);   \
            s2_ = fmaf(fu.x, fv.x, s2_);                                      \
            s2_ = fmaf(fu.y, fv.y, s2_);                                      \
        }                                                                     \
    }                                                                         \
    s2_ += __shfl_xor_sync(0xffffffffu, s2_, 1);                              \
    s2_ += __shfl_xor_sync(0xffffffffu, s2_, 2);                              \
    s2_ += __shfl_xor_sync(0xffffffffu, s2_, 4);                              \
    if (ls == 0 && o < nobs) {                                                \
        float d = vals[o] - s2_;                                              \
        e1sum = fmaf(d, d, e1sum);                                            \
    }                                                                         \
} while (0)

        for (int cc = 0; cc < NCHH; cc++) {
            int s = cc % NSTG;
            if (cc >= NSTG) BAR_SYNC(4 + s);
            uint32_t buf = base + s * STAGEB;
            size_t ko = (size_t)cc * BKC;
            // ---- half 0 of A + all of B in flight ----
            #pragma unroll
            for (int g = 0; g < 8; g++)
                rA[g] = __ldcs((const float4*)(a_base + ko +
                                               (size_t)g * 8 * NDIM));
            #pragma unroll
            for (int g = 0; g < 4; g++)
                rB[g] = *(const uint4*)(b_base + ko + (size_t)g * 16 * NDIM);
            // e1 work rides under the LDG latency
            E1_STEP4(cc * 4 + 0);
            E1_STEP4(cc * 4 + 1);
            // ---- store half 0 + B ----
            #pragma unroll
            for (int g = 0; g < 8; g++) {
                uint32_t lo, hi;
                asm("cvt.rn.bf16x2.f32 %0, %1, %2;" : "=r"(lo)
                    : "f"(rA[g].y), "f"(rA[g].x));
                asm("cvt.rn.bf16x2.f32 %0, %1, %2;" : "=r"(hi)
                    : "f"(rA[g].w), "f"(rA[g].z));
                asm volatile("st.shared.v2.b32 [%0], {%1, %2};"
                             :: "r"(buf + a_st + g * (8 * 144)), "r"(lo),
                                "r"(hi));
            }
            #pragma unroll
            for (int g = 0; g < 4; g++)
                asm volatile("st.shared.v4.b32 [%0], {%1, %2, %3, %4};"
                             :: "r"(buf + A_TILE + b_st + g * (16 * 144)),
                                "r"(rB[g].x), "r"(rB[g].y), "r"(rB[g].z),
                                "r"(rB[g].w));
            // ---- half 1 of A ----
            #pragma unroll
            for (int g = 0; g < 8; g++)
                rA[g] = __ldcs((const float4*)(a_base + ko +
                                               (size_t)(8 + g) * 8 * NDIM));
            E1_STEP4(cc * 4 + 2);
            E1_STEP4(cc * 4 + 3);
            #pragma unroll
            for (int g = 0; g < 8; g++) {
                uint32_t lo, hi;
                asm("cvt.rn.bf16x2.f32 %0, %1, %2;" : "=r"(lo)
                    : "f"(rA[g].y), "f"(rA[g].x));
                asm("cvt.rn.bf16x2.f32 %0, %1, %2;" : "=r"(hi)
                    : "f"(rA[g].w), "f"(rA[g].z));
                asm volatile("st.shared.v2.b32 [%0], {%1, %2};"
                             :: "r"(buf + a_st + (8 + g) * (8 * 144)),
                                "r"(lo), "r"(hi));
            }
            BAR_ARRIVE(1 + s);
        }
#undef E1_STEP4
        #pragma unroll
        for (int o = 16; o; o >>= 1)
            e1sum += __shfl_xor_sync(0xffffffffu, e1sum, o);
        if (lane == 0) { wsum[wid] = 0.f; esum[wid] = e1sum; }
    }

    __syncthreads();
    if (t == 0) {
        float s = 0.f, e = 0.f;
        #pragma unroll
        for (int i = 0; i < QTHREADS / 32; i++) { s += wsum[i]; e += esum[i]; }
        atomicAdd(&g_acc[slot], (double)s);
        atomicAdd(&g_acc[0], (double)e);
        __threadfence();
        unsigned int old = atomicAdd(&g_done, 1u);
        if (old == NCTAS - 1) {                  // last CTA finalizes
            __threadfence();
            g_done = 0;                          // reset for next replay
            double e0 = atomicAdd(&g_acc[0], 0.0);
            double e1 = atomicAdd(&g_acc[1], 0.0);
            double e2 = atomicAdd(&g_acc[2], 0.0);
            double s2 = (double)sigma[0] * (double)sigma[0];
            double E = e0 / (2.0 * s2) + 0.5 * (e1 + e2) +
                       (double)nobs * log(s2);
            out[0] = (float)E;
        }
    }
}

extern "C" void kernel_launch(void* const* d_in, const int* in_sizes, int n_in,
                              void* d_out, int out_size) {
    const float* vals  = (const float*)d_in[0];
    const int*   rows  = (const int*)d_in[1];
    const int*   cols  = (const int*)d_in[2];
    const float* U     = (const float*)d_in[3];
    const float* V     = (const float*)d_in[4];
    const float* sigma = (const float*)d_in[5];
    const float* S_U   = (const float*)d_in[6];
    const float* S_V   = (const float*)d_in[7];
    int nobs = in_sizes[0];
    float* out = (float*)d_out;

    cudaFuncSetAttribute(fused_kernel,
                         cudaFuncAttributeMaxDynamicSharedMemorySize, QSMEM);

    prep_kernel<<<dim3(NDIM / 32, RANK / 32, 2), dim3(32, 32)>>>(V, U);
    fused_kernel<<<dim3(NDIM / BM, 2, 2), QTHREADS, QSMEM>>>(
        S_U, U, S_V, vals, rows, cols, sigma, out, nobs);
}

// round 13
// speedup vs baseline: 1.9583x; 1.9583x over previous
#include <cuda_runtime.h>
#include <cuda_bf16.h>
#include <cstdint>
#include <math.h>

#define NDIM 8192
#define RANK 64
#define BM 128
#define BKC 64
#define KHALF (NDIM / 2)       // 4096
#define NCHH (KHALF / BKC)     // 64 chunks per CTA
#define QTHREADS 256
#define A_TILE (BM * 144)
#define B_TILE (RANK * 144)
#define QSMEM (1024 + 2 * (A_TILE + B_TILE))
#define NCTAS 256

// ---- device scratch (allocation-free rule) ----
__device__ double g_acc[3];                     // [0]=E1, [1]=quad_U, [2]=quad_V
__device__ unsigned int g_done;                 // CTA completion counter
__device__ float  g_Vt[NDIM * RANK];            // V^T fp32 [8192,64]
__device__ __nv_bfloat16 g_Bu[RANK * NDIM];     // U^T bf16 [64,8192] (MMA B)
__device__ __nv_bfloat16 g_Bv[RANK * NDIM];     // V   bf16 [64,8192] (MMA B)
__device__ __nv_bfloat16 g_Ub16[NDIM * RANK];   // U    bf16 [8192,64] (e1)
__device__ __nv_bfloat16 g_Vt16[NDIM * RANK];   // V^T  bf16 [8192,64] (e1)

__device__ __forceinline__ uint32_t smem_u32(const void* p) {
    uint32_t a;
    asm("{ .reg .u64 t; cvta.to.shared.u64 t, %1; cvt.u32.u64 %0, t; }"
        : "=r"(a) : "l"(p));
    return a;
}

// ======================= prep (fused, grid.z selects) =======================
__global__ void prep_kernel(const float* __restrict__ V,
                            const float* __restrict__ U) {
    __shared__ float tile[32][33];
    if (blockIdx.z == 0) {
        int x = blockIdx.x * 32 + threadIdx.x;   // n
        int y = blockIdx.y * 32 + threadIdx.y;   // r
        float v = V[(size_t)y * NDIM + x];
        tile[threadIdx.y][threadIdx.x] = v;
        g_Bv[(size_t)y * NDIM + x] = __float2bfloat16(v);
        __syncthreads();
        int n = blockIdx.x * 32 + threadIdx.y;
        int r = blockIdx.y * 32 + threadIdx.x;
        float tv = tile[threadIdx.x][threadIdx.y];
        g_Vt[(size_t)n * RANK + r] = tv;
        g_Vt16[(size_t)n * RANK + r] = __float2bfloat16(tv);
        if (blockIdx.x == 0 && blockIdx.y == 0 && threadIdx.y == 0 &&
            threadIdx.x < 3)
            g_acc[threadIdx.x] = 0.0;
    } else {
        int i0 = blockIdx.x * 32, r0 = blockIdx.y * 32;
        float u = U[(size_t)(i0 + threadIdx.y) * RANK + r0 + threadIdx.x];
        tile[threadIdx.y][threadIdx.x] = u;
        g_Ub16[(size_t)(i0 + threadIdx.y) * RANK + r0 + threadIdx.x] =
            __float2bfloat16(u);
        __syncthreads();
        g_Bu[(size_t)(r0 + threadIdx.y) * NDIM + i0 + threadIdx.x] =
            __float2bfloat16(tile[threadIdx.x][threadIdx.y]);
    }
}

// ========= fused quad (HMMA bf16) + pipelined cooperative e1 =========
// Quad engine = R11 (159.5us): BM=128, BK=64, 8 warps, 2 smem buffers,
// 1 sync/chunk, 2 CTAs/SM. e1 is now software-pipelined: indices prefetched
// one chunk ahead; gathers issued before COMPUTE, reduced after.
__global__ __launch_bounds__(QTHREADS, 2) void fused_kernel(
    const float* __restrict__ S_U, const float* __restrict__ U,
    const float* __restrict__ S_V, const float* __restrict__ vals,
    const int* __restrict__ rows, const int* __restrict__ cols,
    const float* __restrict__ sigma, float* __restrict__ out, int nobs) {
    extern __shared__ char dynsmem[];
    __shared__ float wsum[QTHREADS / 32];
    __shared__ float esum[QTHREADS / 32];

    const int t = threadIdx.x;
    const int wid = t >> 5, lane = t & 31;

    const float* S;
    const __nv_bfloat16* Bg;
    const float* Xf;
    int slot;
    if (blockIdx.z == 0) { S = S_U; Bg = g_Bu; Xf = U;    slot = 1; }
    else                 { S = S_V; Bg = g_Bv; Xf = g_Vt; slot = 2; }
    const int i0 = blockIdx.x * BM;
    const size_t kbase = (size_t)blockIdx.y * KHALF;
    const int ctaid = blockIdx.x + 64 * blockIdx.y + 128 * blockIdx.z; // 0..255

    // e1: warp covers 512 obs; 8 per chunk (2 groups of 4; 8 lanes per obs).
    const int e1base = ctaid * 4096 + wid * 512;
    const int lg = lane >> 3;          // obs-group within warp (0..3)
    const int ls = lane & 7;           // slice within row (0..7)

    uint32_t base = (smem_u32(dynsmem) + 1023u) & ~1023u;
    uint32_t buf0 = base;
    uint32_t buf1 = base + (A_TILE + B_TILE);

    // ---- closed-form staging bases (register economy) ----
    const float* a_base = S + (size_t)(i0 + (t >> 4)) * NDIM + kbase +
                          (t & 15) * 4;
    const uint32_t a_st = (uint32_t)(t >> 4) * 144 + (t & 15) * 8;
    const __nv_bfloat16* b_base = Bg + (size_t)(t >> 3) * NDIM + kbase +
                                  (t & 7) * 8;
    const uint32_t b_st = (uint32_t)(t >> 3) * 144 + (t & 7) * 16;

    const uint32_t a_lm = (uint32_t)(wid * 16 + (lane & 15)) * 144 + (lane & 16);
    const uint32_t b_lm = (uint32_t)((lane & 7) + ((lane & 16) >> 1)) * 144 +
                          ((lane & 8) << 1);

    float acc[8][4];
    #pragma unroll
    for (int tn = 0; tn < 8; tn++)
        #pragma unroll
        for (int q = 0; q < 4; q++) acc[tn][q] = 0.f;

    float e1sum = 0.f;
    float4 rA[8];
    uint4  rB[2];

    // e1 pipeline state
    int er1, ec1, er2, ec2;            // prefetched indices (current batch)
    float ev1, ev2;                    // prefetched vals
    uint4 ua1, vb1, ua2, vb2;          // in-flight gathers

#define LOADC(k0) do {                                                        \
    _Pragma("unroll") for (int p = 0; p < 8; p++)                             \
        rA[p] = __ldcs((const float4*)(a_base + (k0) +                        \
                                       (size_t)p * 16 * NDIM));               \
    _Pragma("unroll") for (int p = 0; p < 2; p++)                             \
        rB[p] = *(const uint4*)(b_base + (k0) + (size_t)p * 32 * NDIM);       \
} while (0)

#define STOREC(buf) do {                                                      \
    _Pragma("unroll") for (int p = 0; p < 8; p++) {                           \
        uint32_t lo, hi;                                                      \
        asm("cvt.rn.bf16x2.f32 %0, %1, %2;" : "=r"(lo)                        \
            : "f"(rA[p].y), "f"(rA[p].x));                                    \
        asm("cvt.rn.bf16x2.f32 %0, %1, %2;" : "=r"(hi)                        \
            : "f"(rA[p].w), "f"(rA[p].z));                                    \
        asm volatile("st.shared.v2.b32 [%0], {%1, %2};"                       \
                     :: "r"((buf) + a_st + p * (16 * 144)), "r"(lo),          \
                        "r"(hi));                                             \
    }                                                                         \
    _Pragma("unroll") for (int p = 0; p < 2; p++)                             \
        asm volatile("st.shared.v4.b32 [%0], {%1, %2, %3, %4};"               \
                     :: "r"((buf) + A_TILE + b_st + p * (32 * 144)),          \
                        "r"(rB[p].x), "r"(rB[p].y), "r"(rB[p].z),             \
                        "r"(rB[p].w));                                        \
} while (0)

#define COMPUTE(buf) do {                                                     \
    uint32_t ab = (buf), bb = (buf) + A_TILE;                                 \
    _Pragma("unroll") for (int s = 0; s < 4; s++) {                           \
        uint32_t a[4];                                                        \
        asm volatile("ldmatrix.sync.aligned.m8n8.x4.shared.b16 "              \
                     "{%0,%1,%2,%3}, [%4];"                                   \
                     : "=r"(a[0]), "=r"(a[1]), "=r"(a[2]), "=r"(a[3])         \
                     : "r"(ab + a_lm + s * 32));                              \
        uint32_t b[4][4];                                                     \
        _Pragma("unroll") for (int j = 0; j < 4; j++)                         \
            asm volatile("ldmatrix.sync.aligned.m8n8.x4.shared.b16 "          \
                         "{%0,%1,%2,%3}, [%4];"                               \
                         : "=r"(b[j][0]), "=r"(b[j][1]),                      \
                           "=r"(b[j][2]), "=r"(b[j][3])                       \
                         : "r"(bb + b_lm + j * (16 * 144) + s * 32));         \
        _Pragma("unroll") for (int tn = 0; tn < 8; tn++)                      \
            asm volatile("mma.sync.aligned.m16n8k16.row.col.f32.bf16.bf16.f32 " \
                         "{%0,%1,%2,%3}, {%4,%5,%6,%7}, {%8,%9}, "            \
                         "{%0,%1,%2,%3};"                                     \
                         : "+f"(acc[tn][0]), "+f"(acc[tn][1]),                \
                           "+f"(acc[tn][2]), "+f"(acc[tn][3])                 \
                         : "r"(a[0]), "r"(a[1]), "r"(a[2]), "r"(a[3]),        \
                           "r"(b[tn >> 1][(tn & 1) * 2]),                     \
                           "r"(b[tn >> 1][(tn & 1) * 2 + 1]));                \
    }                                                                         \
} while (0)

// prefetch indices + vals for chunk j's 8 obs (clamped)
#define E1_IDX(j) do {                                                        \
    int o1 = e1base + (j) * 8 + lg;                                           \
    int o2 = o1 + 4;                                                          \
    int o1c = o1 < nobs ? o1 : nobs - 1;                                      \
    int o2c = o2 < nobs ? o2 : nobs - 1;                                      \
    er1 = rows[o1c]; ec1 = cols[o1c]; ev1 = vals[o1c];                        \
    er2 = rows[o2c]; ec2 = cols[o2c]; ev2 = vals[o2c];                        \
} while (0)

// issue gathers for the current batch (indices already resident)
#define E1_GATHER() do {                                                      \
    ua1 = *(const uint4*)(g_Ub16 + (size_t)er1 * RANK + ls * 8);              \
    vb1 = *(const uint4*)(g_Vt16 + (size_t)ec1 * RANK + ls * 8);              \
    ua2 = *(const uint4*)(g_Ub16 + (size_t)er2 * RANK + ls * 8);              \
    vb2 = *(const uint4*)(g_Vt16 + (size_t)ec2 * RANK + ls * 8);              \
} while (0)

#define E1_DOT(UA, VB, OUT) do {                                              \
    float s_ = 0.f;                                                           \
    const uint32_t* up = &(UA).x;                                             \
    const uint32_t* vp = &(VB).x;                                             \
    _Pragma("unroll") for (int h = 0; h < 4; h++) {                           \
        float2 fu = __bfloat1622float2(*(const __nv_bfloat162*)&up[h]);       \
        float2 fv = __bfloat1622float2(*(const __nv_bfloat162*)&vp[h]);       \
        s_ = fmaf(fu.x, fv.x, s_);                                            \
        s_ = fmaf(fu.y, fv.y, s_);                                            \
    }                                                                         \
    s_ += __shfl_xor_sync(0xffffffffu, s_, 1);                                \
    s_ += __shfl_xor_sync(0xffffffffu, s_, 2);                                \
    s_ += __shfl_xor_sync(0xffffffffu, s_, 4);                                \
    OUT = s_;                                                                 \
} while (0)

// reduce current batch (gathers complete by now); vv1/vv2 captured pre-IDX
#define E1_REDUCE(j, vv1, vv2) do {                                           \
    float p1, p2;                                                             \
    E1_DOT(ua1, vb1, p1);                                                     \
    E1_DOT(ua2, vb2, p2);                                                     \
    if (ls == 0) {                                                            \
        int o1 = e1base + (j) * 8 + lg;                                       \
        if (o1 < nobs) {                                                      \
            float d = (vv1) - p1;                                             \
            e1sum = fmaf(d, d, e1sum);                                        \
        }                                                                     \
        if (o1 + 4 < nobs) {                                                  \
            float d = (vv2) - p2;                                             \
            e1sum = fmaf(d, d, e1sum);                                        \
        }                                                                     \
    }                                                                         \
} while (0)

    // prologue
    E1_IDX(0);
    LOADC(0);
    STOREC(buf0);
    __syncthreads();

    // steady: load(cc+1) | e1 gathers | idx prefetch(cc+1) | compute(cc) |
    //         e1 reduce(cc) | store(cc+1) | 1 sync
    for (int cc = 0; cc < NCHH; cc++) {
        uint32_t cur = (cc & 1) ? buf1 : buf0;
        uint32_t nxt = (cc & 1) ? buf0 : buf1;
        if (cc + 1 < NCHH) LOADC((size_t)(cc + 1) * BKC);
        E1_GATHER();
        float vv1 = ev1, vv2 = ev2;
        if (cc + 1 < NCHH) E1_IDX(cc + 1);
        COMPUTE(cur);
        E1_REDUCE(cc, vv1, vv2);
        if (cc + 1 < NCHH) {
            STOREC(nxt);
            __syncthreads();
        }
    }

    // quad epilogue: partial = sum of D[row][n] * X[row][n]
    const int g = lane >> 2, tg = lane & 3;
    const int r0 = i0 + wid * 16 + g;
    float partial = 0.f;
    #pragma unroll
    for (int tn = 0; tn < 8; tn++) {
        int n = tn * 8 + 2 * tg;
        float2 x0 = *(const float2*)(Xf + (size_t)r0 * RANK + n);
        float2 x1 = *(const float2*)(Xf + (size_t)(r0 + 8) * RANK + n);
        partial = fmaf(acc[tn][0], x0.x, partial);
        partial = fmaf(acc[tn][1], x0.y, partial);
        partial = fmaf(acc[tn][2], x1.x, partial);
        partial = fmaf(acc[tn][3], x1.y, partial);
    }
    #pragma unroll
    for (int o = 16; o; o >>= 1) {
        partial += __shfl_xor_sync(0xffffffffu, partial, o);
        e1sum   += __shfl_xor_sync(0xffffffffu, e1sum, o);
    }
    if (lane == 0) { wsum[wid] = partial; esum[wid] = e1sum; }
    __syncthreads();
    if (t == 0) {
        float s = 0.f, e = 0.f;
        #pragma unroll
        for (int i = 0; i < QTHREADS / 32; i++) { s += wsum[i]; e += esum[i]; }
        atomicAdd(&g_acc[slot], (double)s);
        atomicAdd(&g_acc[0], (double)e);
        __threadfence();
        unsigned int old = atomicAdd(&g_done, 1u);
        if (old == NCTAS - 1) {                  // last CTA finalizes
            __threadfence();
            g_done = 0;                          // reset for next replay
            double e0 = atomicAdd(&g_acc[0], 0.0);
            double e1 = atomicAdd(&g_acc[1], 0.0);
            double e2 = atomicAdd(&g_acc[2], 0.0);
            double s2 = (double)sigma[0] * (double)sigma[0];
            double E = e0 / (2.0 * s2) + 0.5 * (e1 + e2) +
                       (double)nobs * log(s2);
            out[0] = (float)E;
        }
    }
#undef LOADC
#undef STOREC
#undef COMPUTE
#undef E1_IDX
#undef E1_GATHER
#undef E1_DOT
#undef E1_REDUCE
}

extern "C" void kernel_launch(void* const* d_in, const int* in_sizes, int n_in,
                              void* d_out, int out_size) {
    const float* vals  = (const float*)d_in[0];
    const int*   rows  = (const int*)d_in[1];
    const int*   cols  = (const int*)d_in[2];
    const float* U     = (const float*)d_in[3];
    const float* V     = (const float*)d_in[4];
    const float* sigma = (const float*)d_in[5];
    const float* S_U   = (const float*)d_in[6];
    const float* S_V   = (const float*)d_in[7];
    int nobs = in_sizes[0];
    float* out = (float*)d_out;

    cudaFuncSetAttribute(fused_kernel,
                         cudaFuncAttributeMaxDynamicSharedMemorySize, QSMEM);

    prep_kernel<<<dim3(NDIM / 32, RANK / 32, 2), dim3(32, 32)>>>(V, U);
    fused_kernel<<<dim3(NDIM / BM, 2, 2), QTHREADS, QSMEM>>>(
        S_U, U, S_V, vals, rows, cols, sigma, out, nobs);
}